// round 10
// baseline (speedup 1.0000x reference)
#include <cuda_runtime.h>
#include <cstdint>

// ---------------------------------------------------------------------------
// Fused IGCNet conv, mma.sync 3xTF32, WARP-LOCAL pipeline (no mid-kernel
// block syncs). Block: 128 threads / 4 warps / 8 nodes / 128 edges.
// Warp w owns edges 32w..32w+31 == nodes 2w,2w+1:
//   GEMM1: A_w[32,40] x W1[64,40]^T -> H_w[32,64] (per-warp smem)
//   GEMM2: H_w[32,64] x W2[32,64]^T -> C-frags; segment-max via shfl_xor
//   (bias+relu folded post-max), node MLP fp32 SIMT, norm clip, concat.
// One __syncthreads (weight staging); everything else __syncwarp.
// ---------------------------------------------------------------------------

#define NMAX 100000
__device__ float g_buf0[(size_t)NMAX * 32];
__device__ float g_buf1[(size_t)NMAX * 32];

// ---- smem layout (float offsets) ----
#define OFF_A     0        // 4 x [32][40] per-warp A tiles (swizzled)   5120
#define OFF_H     5120     // 4 x [32][72] per-warp H tiles (swizzled)   9216
#define OFF_W1    14336    // [64][40] swizzled                          2560
#define OFF_W2    16896    // [32][72] swizzled                          2304
#define OFF_W3    19200    // [64][72] swizzled                          4608
#define OFF_XIN   23808    // [8][64] = [x_i(32) | aggr(32)]              512
#define OFF_HID   24320    // [8][64] node-MLP hidden                     512
#define OFF_B1    24832
#define OFF_B2    24896
#define OFF_B3    24928
#define OFF_B4    24992
#define SMEM_FLOATS 25008  // 100032 B -> 2 blocks/SM

__device__ __forceinline__ uint32_t f2tf(float f) {
    uint32_t u;
    asm("cvt.rna.tf32.f32 %0, %1;" : "=r"(u) : "f"(f));
    return u;
}
__device__ __forceinline__ void split_tf(float f, uint32_t& hi, uint32_t& lo) {
    hi = f2tf(f);
    lo = f2tf(f - __uint_as_float(hi));
}
__device__ __forceinline__ void mma8(float* c, const uint32_t* a, const uint32_t* b) {
    asm volatile(
        "mma.sync.aligned.m16n8k8.row.col.f32.tf32.tf32.f32 "
        "{%0,%1,%2,%3}, {%4,%5,%6,%7}, {%8,%9}, {%0,%1,%2,%3};"
        : "+f"(c[0]), "+f"(c[1]), "+f"(c[2]), "+f"(c[3])
        : "r"(a[0]), "r"(a[1]), "r"(a[2]), "r"(a[3]), "r"(b[0]), "r"(b[1]));
}
// swizzle for 40-col tiles (A, W1): cols 0..31 3-bit XOR, cols 32..39 1-bit
__device__ __forceinline__ int swA(int c, int x) {
    return (c < 32) ? (c ^ x) : (32 + ((c - 32) ^ (x & 4)));
}

__global__ void __launch_bounds__(128, 2) conv_kernel(
    const float* __restrict__ h_in, float* __restrict__ h_out,
    const int* __restrict__ src, const float* __restrict__ edge_attr,
    const float* __restrict__ w11, const float* __restrict__ b11,
    const float* __restrict__ w12, const float* __restrict__ b12,
    const float* __restrict__ w21, const float* __restrict__ b21,
    const float* __restrict__ w22, const float* __restrict__ b22)
{
    extern __shared__ float s[];
    const int tid = threadIdx.x;
    const int wid = tid >> 5, l = tid & 31;
    const int n0 = blockIdx.x * 8;

    // ---- gather (warp-local): edge 32*wid + l -> per-warp A tile ----
    {
        const long long eg = (long long)blockIdx.x * 128 + 32 * wid + l;
        const int si = src[eg];
        const float4* xr = (const float4*)(h_in + (size_t)si * 32);
        const int xa = ((l >> 2) & 7) << 2;
        const int rb = OFF_A + wid * 1280 + l * 40;
        #pragma unroll
        for (int j = 0; j < 8; j++)
            *(float4*)&s[rb + ((4 * j) ^ xa)] = xr[j];
        const float4* ar = (const float4*)(edge_attr + (size_t)eg * 8);
        #pragma unroll
        for (int j = 0; j < 2; j++)
            *(float4*)&s[rb + 32 + ((4 * j) ^ (xa & 4))] = ar[j];
        if (l < 16) {  // x_i for this warp's 2 nodes -> XIN[:, 0:32]
            const int nd = 2 * wid + (l >> 3), q = l & 7;
            float4 v = *(const float4*)(h_in + (size_t)(n0 + nd) * 32 + q * 4);
            *(float4*)&s[OFF_XIN + nd * 64 + q * 4] = v;
        }
    }

    // ---- stage weights (block-wide, behind the single sync) ----
    for (int i = tid; i < 2560; i += 128) {
        int n = i / 40, k = i - 40 * n;
        s[OFF_W1 + n * 40 + swA(k, ((n >> 2) & 7) << 2)] = w11[i];
    }
    for (int i = tid; i < 2048; i += 128) {
        int n = i >> 6, k = i & 63;
        s[OFF_W2 + n * 72 + (k ^ (((n >> 2) & 7) << 2))] = w12[i];
    }
    for (int i4 = tid; i4 < 1024; i4 += 128) {
        const int h = i4 >> 4, cb = (i4 & 15) * 4;
        float4 v = __ldg((const float4*)(w21 + h * 64 + cb));
        *(float4*)&s[OFF_W3 + h * 72 + (cb ^ (((h >> 2) & 7) << 2))] = v;
    }
    if (tid < 64) s[OFF_B1 + tid] = b11[tid];
    if (tid < 32) s[OFF_B2 + tid] = b12[tid];
    if (tid < 64) s[OFF_B3 + tid] = b21[tid];
    if (tid < 16) s[OFF_B4 + tid] = b22[tid];
    __syncthreads();   // the ONLY block-wide sync

    const int lr = l >> 2, lc = l & 3;
    // local rows (within this warp's 32-row tiles) + swizzle masks
    int r0m[2], r1m[2], x0m[2], x1m[2];
    #pragma unroll
    for (int mt = 0; mt < 2; mt++) {
        r0m[mt] = 16 * mt + lr;
        r1m[mt] = r0m[mt] + 8;
        x0m[mt] = ((r0m[mt] >> 2) & 7) << 2;
        x1m[mt] = ((r1m[mt] >> 2) & 7) << 2;
    }
    const int aw = OFF_A + wid * 1280;
    const int hw = OFF_H + wid * 2304;

    // ---- GEMM1: A_w[32,40] x W1^T -> acc[2][8][4], 3xTF32 ----
    float acc[2][8][4];
    #pragma unroll
    for (int mt = 0; mt < 2; mt++)
        #pragma unroll
        for (int nt = 0; nt < 8; nt++)
            #pragma unroll
            for (int q = 0; q < 4; q++) acc[mt][nt][q] = 0.f;

    #pragma unroll
    for (int kc = 0; kc < 5; kc++) {
        const int c0 = 8 * kc + lc, c1 = c0 + 4;
        uint32_t ah[2][4], al[2][4];
        #pragma unroll
        for (int mt = 0; mt < 2; mt++) {
            split_tf(s[aw + r0m[mt] * 40 + swA(c0, x0m[mt])], ah[mt][0], al[mt][0]);
            split_tf(s[aw + r1m[mt] * 40 + swA(c0, x1m[mt])], ah[mt][1], al[mt][1]);
            split_tf(s[aw + r0m[mt] * 40 + swA(c1, x0m[mt])], ah[mt][2], al[mt][2]);
            split_tf(s[aw + r1m[mt] * 40 + swA(c1, x1m[mt])], ah[mt][3], al[mt][3]);
        }
        #pragma unroll
        for (int nt = 0; nt < 8; nt++) {
            const int wr = 8 * nt + lr;
            const int xw = ((wr >> 2) & 7) << 2;
            uint32_t bh[2], bl[2];
            split_tf(s[OFF_W1 + wr * 40 + swA(c0, xw)], bh[0], bl[0]);
            split_tf(s[OFF_W1 + wr * 40 + swA(c1, xw)], bh[1], bl[1]);
            #pragma unroll
            for (int mt = 0; mt < 2; mt++) {
                mma8(acc[mt][nt], ah[mt], bh);
                mma8(acc[mt][nt], al[mt], bh);
                mma8(acc[mt][nt], ah[mt], bl);
            }
        }
    }

    // ---- H = relu(acc + b1) -> per-warp swizzled smem ----
    #pragma unroll
    for (int mt = 0; mt < 2; mt++) {
        #pragma unroll
        for (int nt = 0; nt < 8; nt++) {
            const int c0 = 8 * nt + 2 * lc;
            const float bv0 = s[OFF_B1 + c0], bv1 = s[OFF_B1 + c0 + 1];
            float2 v01 = make_float2(fmaxf(acc[mt][nt][0] + bv0, 0.f),
                                     fmaxf(acc[mt][nt][1] + bv1, 0.f));
            float2 v23 = make_float2(fmaxf(acc[mt][nt][2] + bv0, 0.f),
                                     fmaxf(acc[mt][nt][3] + bv1, 0.f));
            *(float2*)&s[hw + r0m[mt] * 72 + (c0 ^ x0m[mt])] = v01;
            *(float2*)&s[hw + r1m[mt] * 72 + (c0 ^ x1m[mt])] = v23;
        }
    }
    __syncwarp();

    // ---- GEMM2: H_w[32,64] x W2^T -> acc2[2][4][4], 3xTF32 ----
    float acc2[2][4][4];
    #pragma unroll
    for (int mt = 0; mt < 2; mt++)
        #pragma unroll
        for (int nt = 0; nt < 4; nt++)
            #pragma unroll
            for (int q = 0; q < 4; q++) acc2[mt][nt][q] = 0.f;

    #pragma unroll
    for (int kc = 0; kc < 8; kc++) {
        const int c0 = 8 * kc + lc, c1 = c0 + 4;
        uint32_t ah[2][4], al[2][4];
        #pragma unroll
        for (int mt = 0; mt < 2; mt++) {
            split_tf(s[hw + r0m[mt] * 72 + (c0 ^ x0m[mt])], ah[mt][0], al[mt][0]);
            split_tf(s[hw + r1m[mt] * 72 + (c0 ^ x1m[mt])], ah[mt][1], al[mt][1]);
            split_tf(s[hw + r0m[mt] * 72 + (c1 ^ x0m[mt])], ah[mt][2], al[mt][2]);
            split_tf(s[hw + r1m[mt] * 72 + (c1 ^ x1m[mt])], ah[mt][3], al[mt][3]);
        }
        #pragma unroll
        for (int nt = 0; nt < 4; nt++) {
            const int wr = 8 * nt + lr;
            const int xw = ((wr >> 2) & 7) << 2;
            uint32_t bh[2], bl[2];
            split_tf(s[OFF_W2 + wr * 72 + (c0 ^ xw)], bh[0], bl[0]);
            split_tf(s[OFF_W2 + wr * 72 + (c1 ^ xw)], bh[1], bl[1]);
            #pragma unroll
            for (int mt = 0; mt < 2; mt++) {
                mma8(acc2[mt][nt], ah[mt], bh);
                mma8(acc2[mt][nt], al[mt], bh);
                mma8(acc2[mt][nt], ah[mt], bl);
            }
        }
    }

    // ---- segment max via shfl_xor (tile mt == node 2*wid+mt) ----
    // max over 16 rows, then bias+relu once (monotone: relu(max+b))
    #pragma unroll
    for (int mt = 0; mt < 2; mt++) {
        const int ndm = 2 * wid + mt;
        #pragma unroll
        for (int nt = 0; nt < 4; nt++) {
            float m0 = fmaxf(acc2[mt][nt][0], acc2[mt][nt][2]);
            float m1 = fmaxf(acc2[mt][nt][1], acc2[mt][nt][3]);
            #pragma unroll
            for (int off = 4; off <= 16; off <<= 1) {
                m0 = fmaxf(m0, __shfl_xor_sync(0xffffffffu, m0, off));
                m1 = fmaxf(m1, __shfl_xor_sync(0xffffffffu, m1, off));
            }
            if (l < 4) {   // lr==0 lanes write cols 8nt+2l, +1
                const int c0 = 8 * nt + 2 * l;
                s[OFF_XIN + ndm * 64 + 32 + c0]     = fmaxf(m0 + s[OFF_B2 + c0], 0.f);
                s[OFF_XIN + ndm * 64 + 32 + c0 + 1] = fmaxf(m1 + s[OFF_B2 + c0 + 1], 0.f);
            }
        }
    }
    __syncwarp();

    // ---- node MLP (warp-local): lane -> (node 2*wid + l/16, output l%16) ----
    {
        const int nd = 2 * wid + (l >> 4), q = l & 15;
        const int c4 = q * 4;
        const int xq = (q & 7) << 2;
        float ha[4];
        #pragma unroll
        for (int j = 0; j < 4; j++) ha[j] = s[OFF_B3 + c4 + j];
        #pragma unroll
        for (int k4 = 0; k4 < 16; k4++) {
            const float4 xv = *(const float4*)&s[OFF_XIN + nd * 64 + 4 * k4];
            #pragma unroll
            for (int j = 0; j < 4; j++) {
                const float4 wv = *(const float4*)&s[OFF_W3 + (c4 + j) * 72 + ((4 * k4) ^ xq)];
                ha[j] = fmaf(xv.x, wv.x, fmaf(xv.y, wv.y, fmaf(xv.z, wv.z, fmaf(xv.w, wv.w, ha[j]))));
            }
        }
        *(float4*)&s[OFF_HID + nd * 64 + c4] = make_float4(
            fmaxf(ha[0], 0.f), fmaxf(ha[1], 0.f), fmaxf(ha[2], 0.f), fmaxf(ha[3], 0.f));
        __syncwarp();

        float a3 = s[OFF_B4 + q];
        #pragma unroll
        for (int k4 = 0; k4 < 16; k4++) {
            const float4 hv = *(const float4*)&s[OFF_HID + nd * 64 + 4 * k4];
            const float4 wv = __ldg((const float4*)(w22 + q * 64 + 4 * k4));
            a3 = fmaf(hv.x, wv.x, fmaf(hv.y, wv.y, fmaf(hv.z, wv.z, fmaf(hv.w, wv.w, a3))));
        }
        float v = fmaxf(a3, 0.f);
        float ssq = v * v;
        ssq += __shfl_xor_sync(0xffffffffu, ssq, 1);
        ssq += __shfl_xor_sync(0xffffffffu, ssq, 2);
        ssq += __shfl_xor_sync(0xffffffffu, ssq, 4);
        ssq += __shfl_xor_sync(0xffffffffu, ssq, 8);
        const float sn = sqrtf(ssq);
        if (sn > 1.f) v = v / sn;
        const size_t ng = (size_t)(n0 + nd);
        h_out[ng * 32 + q]      = v;
        h_out[ng * 32 + 16 + q] = s[OFF_XIN + nd * 64 + q];  // x[:, :16]
    }
}

extern "C" void kernel_launch(void* const* d_in, const int* in_sizes, int n_in,
                              void* d_out, int out_size)
{
    const float* x     = (const float*)d_in[0];
    const int*   eidx  = (const int*)d_in[1];     // [2, E] int32
    const float* eattr = (const float*)d_in[2];
    const float* w11 = (const float*)d_in[3];
    const float* b11 = (const float*)d_in[4];
    const float* w12 = (const float*)d_in[5];
    const float* b12 = (const float*)d_in[6];
    const float* w21 = (const float*)d_in[7];
    const float* b21 = (const float*)d_in[8];
    const float* w22 = (const float*)d_in[9];
    const float* b22 = (const float*)d_in[10];

    const int nN = in_sizes[0] / 32;          // 100000
    const int* srcp = eidx;                   // row 0 = src
    const int grid = nN / 8;                  // 12500 blocks (8 nodes each)
    const size_t smem = (size_t)SMEM_FLOATS * sizeof(float);

    cudaFuncSetAttribute(conv_kernel, cudaFuncAttributeMaxDynamicSharedMemorySize, (int)smem);

    float *b0, *b1;
    cudaGetSymbolAddress((void**)&b0, g_buf0);
    cudaGetSymbolAddress((void**)&b1, g_buf1);

    conv_kernel<<<grid, 128, smem>>>(x,  b0, srcp, eattr, w11, b11, w12, b12, w21, b21, w22, b22);
    conv_kernel<<<grid, 128, smem>>>(b0, b1, srcp, eattr, w11, b11, w12, b12, w21, b21, w22, b22);
    conv_kernel<<<grid, 128, smem>>>(b1, (float*)d_out, srcp, eattr, w11, b11, w12, b12, w21, b21, w22, b22);
}

// round 11
// speedup vs baseline: 1.5614x; 1.5614x over previous
#include <cuda_runtime.h>
#include <cstdint>

// ---------------------------------------------------------------------------
// Fused IGCNet conv, mma.sync 3xTF32 (mask-split), 128-edge blocks.
// Block: 8 nodes, 128 edges, 4 warps, occ 4 (48.8KB smem).
//   GEMM1: A[128,40] x W1[64,40]^T -> H[128,64] (swizzled smem)
//   GEMM2: H[128,64] x W2[32,64]^T -> C-frags -> shfl-xor segment max
//          (bias+relu folded post-max) -> aggr
//   node MLP fp32 SIMT (W3 staged into dead H region), norm clip, concat.
// R11: cvt.rna.tf32 split replaced by LOP3 mask + exact FSUB; msgT smem
//      phase eliminated via fragment-level shfl reduction (6 -> 4 barriers).
// ---------------------------------------------------------------------------

#define NMAX 100000
__device__ float g_buf0[(size_t)NMAX * 32];
__device__ float g_buf1[(size_t)NMAX * 32];

// ---- smem layout (float offsets) ----
// U (9216): phase1 A[128][40](5120)+W1[64][40](@5120,2560); phase2 H[128][72];
//           phase3 W3[64][72](@0,4608)
#define OFF_U     0
#define OFF_W1    5120
#define OFF_W2S   9216     // [32][72] = 2304; later hid[8][64]
#define OFF_XIN   11520    // [8][64] = [x_i(32) | aggr(32)]
#define OFF_B1    12032
#define OFF_B2    12096
#define OFF_B3    12128
#define OFF_B4    12192
#define SMEM_FLOATS 12208  // 48832 B -> 4 blocks/SM

// mask split: hi = x with low 13 mantissa bits cleared (exactly tf32-representable),
// lo = x - hi (exact FSUB). LOP3+FADD (lat 4) instead of 2x cvt (lat ~20).
__device__ __forceinline__ void split_tf(float f, uint32_t& hi, uint32_t& lo) {
    hi = __float_as_uint(f) & 0xFFFFE000u;
    lo = __float_as_uint(f - __uint_as_float(hi));
}
__device__ __forceinline__ void mma8(float* c, const uint32_t* a, const uint32_t* b) {
    asm volatile(
        "mma.sync.aligned.m16n8k8.row.col.f32.tf32.tf32.f32 "
        "{%0,%1,%2,%3}, {%4,%5,%6,%7}, {%8,%9}, {%0,%1,%2,%3};"
        : "+f"(c[0]), "+f"(c[1]), "+f"(c[2]), "+f"(c[3])
        : "r"(a[0]), "r"(a[1]), "r"(a[2]), "r"(a[3]), "r"(b[0]), "r"(b[1]));
}
// swizzle for 40-col tiles (A, W1): cols 0..31 3-bit XOR, cols 32..39 1-bit
__device__ __forceinline__ int swA(int c, int x) {
    return (c < 32) ? (c ^ x) : (32 + ((c - 32) ^ (x & 4)));
}

__global__ void __launch_bounds__(128, 4) conv_kernel(
    const float* __restrict__ h_in, float* __restrict__ h_out,
    const int* __restrict__ src, const float* __restrict__ edge_attr,
    const float* __restrict__ w11, const float* __restrict__ b11,
    const float* __restrict__ w12, const float* __restrict__ b12,
    const float* __restrict__ w21, const float* __restrict__ b21,
    const float* __restrict__ w22, const float* __restrict__ b22)
{
    extern __shared__ float s[];
    const int tid = threadIdx.x;
    const int wid = tid >> 5, l = tid & 31;
    const int n0 = blockIdx.x * 8;

    // ---- stage W1/W2 (swizzled) + biases ----
    for (int i = tid; i < 2560; i += 128) {
        int n = i / 40, k = i - 40 * n;
        s[OFF_W1 + n * 40 + swA(k, ((n >> 2) & 7) << 2)] = w11[i];
    }
    for (int i = tid; i < 2048; i += 128) {
        int n = i >> 6, k = i & 63;
        s[OFF_W2S + n * 72 + (k ^ (((n >> 2) & 7) << 2))] = w12[i];
    }
    if (tid < 64) s[OFF_B1 + tid] = b11[tid];
    if (tid < 32) s[OFF_B2 + tid] = b12[tid];
    if (tid < 64) s[OFF_B3 + tid] = b21[tid];
    if (tid < 16) s[OFF_B4 + tid] = b22[tid];

    // ---- gather: A[e][k] stride 40 swizzled (thread = edge) ----
    {
        const long long eg = (long long)blockIdx.x * 128 + tid;
        const int si = src[eg];
        const float4* xr = (const float4*)(h_in + (size_t)si * 32);
        const int xa = ((tid >> 2) & 7) << 2;
        const int rb = OFF_U + tid * 40;
        #pragma unroll
        for (int j = 0; j < 8; j++)
            *(float4*)&s[rb + ((4 * j) ^ xa)] = xr[j];
        const float4* ar = (const float4*)(edge_attr + (size_t)eg * 8);
        #pragma unroll
        for (int j = 0; j < 2; j++)
            *(float4*)&s[rb + 32 + ((4 * j) ^ (xa & 4))] = ar[j];
        if (tid < 64) {  // destination-node features -> Xin[:, 0:32]
            int nd = tid >> 3, q = tid & 7;
            float4 v = *(const float4*)(h_in + (size_t)(n0 + nd) * 32 + q * 4);
            *(float4*)&s[OFF_XIN + nd * 64 + q * 4] = v;
        }
    }
    __syncthreads();   // S1

    const int e0 = 32 * wid;
    const int lr = l >> 2, lc = l & 3;
    int r0m[2], r1m[2], x0m[2], x1m[2];
    #pragma unroll
    for (int mt = 0; mt < 2; mt++) {
        r0m[mt] = e0 + 16 * mt + lr;
        r1m[mt] = r0m[mt] + 8;
        x0m[mt] = ((r0m[mt] >> 2) & 7) << 2;
        x1m[mt] = ((r1m[mt] >> 2) & 7) << 2;
    }

    // ---- GEMM1: A[128,40] x W1^T -> acc[2][8][4], 3xTF32 ----
    float acc[2][8][4];
    #pragma unroll
    for (int mt = 0; mt < 2; mt++)
        #pragma unroll
        for (int nt = 0; nt < 8; nt++)
            #pragma unroll
            for (int q = 0; q < 4; q++) acc[mt][nt][q] = 0.f;

    #pragma unroll
    for (int kc = 0; kc < 5; kc++) {
        const int c0 = 8 * kc + lc, c1 = c0 + 4;
        uint32_t ah[2][4], al[2][4];
        #pragma unroll
        for (int mt = 0; mt < 2; mt++) {
            split_tf(s[OFF_U + r0m[mt] * 40 + swA(c0, x0m[mt])], ah[mt][0], al[mt][0]);
            split_tf(s[OFF_U + r1m[mt] * 40 + swA(c0, x1m[mt])], ah[mt][1], al[mt][1]);
            split_tf(s[OFF_U + r0m[mt] * 40 + swA(c1, x0m[mt])], ah[mt][2], al[mt][2]);
            split_tf(s[OFF_U + r1m[mt] * 40 + swA(c1, x1m[mt])], ah[mt][3], al[mt][3]);
        }
        #pragma unroll
        for (int nt = 0; nt < 8; nt++) {
            const int wr = 8 * nt + lr;
            const int xw = ((wr >> 2) & 7) << 2;
            uint32_t bh[2], bl[2];
            split_tf(s[OFF_W1 + wr * 40 + swA(c0, xw)], bh[0], bl[0]);
            split_tf(s[OFF_W1 + wr * 40 + swA(c1, xw)], bh[1], bl[1]);
            #pragma unroll
            for (int mt = 0; mt < 2; mt++) {
                mma8(acc[mt][nt], ah[mt], bh);
                mma8(acc[mt][nt], al[mt], bh);
                mma8(acc[mt][nt], ah[mt], bl);
            }
        }
    }
    __syncthreads();   // S2: A/W1 reads done everywhere; U becomes H[128][72]

    // ---- H = relu(acc + b1) -> swizzled smem (float2 stores) ----
    #pragma unroll
    for (int mt = 0; mt < 2; mt++) {
        #pragma unroll
        for (int nt = 0; nt < 8; nt++) {
            const int c0 = 8 * nt + 2 * lc;
            const float bv0 = s[OFF_B1 + c0], bv1 = s[OFF_B1 + c0 + 1];
            float2 v01 = make_float2(fmaxf(acc[mt][nt][0] + bv0, 0.f),
                                     fmaxf(acc[mt][nt][1] + bv1, 0.f));
            float2 v23 = make_float2(fmaxf(acc[mt][nt][2] + bv0, 0.f),
                                     fmaxf(acc[mt][nt][3] + bv1, 0.f));
            *(float2*)&s[OFF_U + r0m[mt] * 72 + (c0 ^ x0m[mt])] = v01;
            *(float2*)&s[OFF_U + r1m[mt] * 72 + (c0 ^ x1m[mt])] = v23;
        }
    }
    __syncwarp();   // GEMM2 reads only this warp's own H rows

    // ---- GEMM2: H[128,64] x W2^T -> acc2[2][4][4], 3xTF32 ----
    float acc2[2][4][4];
    #pragma unroll
    for (int mt = 0; mt < 2; mt++)
        #pragma unroll
        for (int nt = 0; nt < 4; nt++)
            #pragma unroll
            for (int q = 0; q < 4; q++) acc2[mt][nt][q] = 0.f;

    #pragma unroll
    for (int kc = 0; kc < 8; kc++) {
        const int c0 = 8 * kc + lc, c1 = c0 + 4;
        uint32_t ah[2][4], al[2][4];
        #pragma unroll
        for (int mt = 0; mt < 2; mt++) {
            split_tf(s[OFF_U + r0m[mt] * 72 + (c0 ^ x0m[mt])], ah[mt][0], al[mt][0]);
            split_tf(s[OFF_U + r1m[mt] * 72 + (c0 ^ x1m[mt])], ah[mt][1], al[mt][1]);
            split_tf(s[OFF_U + r0m[mt] * 72 + (c1 ^ x0m[mt])], ah[mt][2], al[mt][2]);
            split_tf(s[OFF_U + r1m[mt] * 72 + (c1 ^ x1m[mt])], ah[mt][3], al[mt][3]);
        }
        #pragma unroll
        for (int nt = 0; nt < 4; nt++) {
            const int wr = 8 * nt + lr;
            const int xw = ((wr >> 2) & 7) << 2;
            uint32_t bh[2], bl[2];
            split_tf(s[OFF_W2S + wr * 72 + (c0 ^ xw)], bh[0], bl[0]);
            split_tf(s[OFF_W2S + wr * 72 + (c1 ^ xw)], bh[1], bl[1]);
            #pragma unroll
            for (int mt = 0; mt < 2; mt++) {
                mma8(acc2[mt][nt], ah[mt], bh);
                mma8(acc2[mt][nt], al[mt], bh);
                mma8(acc2[mt][nt], ah[mt], bl);
            }
        }
    }

    // ---- segment max via shfl_xor (tile mt == node 2*wid+mt) ----
    // max over 16 rows of the C fragment, then bias+relu once (monotone).
    #pragma unroll
    for (int mt = 0; mt < 2; mt++) {
        const int ndm = 2 * wid + mt;
        #pragma unroll
        for (int nt = 0; nt < 4; nt++) {
            float m0 = fmaxf(acc2[mt][nt][0], acc2[mt][nt][2]);
            float m1 = fmaxf(acc2[mt][nt][1], acc2[mt][nt][3]);
            #pragma unroll
            for (int off = 4; off <= 16; off <<= 1) {
                m0 = fmaxf(m0, __shfl_xor_sync(0xffffffffu, m0, off));
                m1 = fmaxf(m1, __shfl_xor_sync(0xffffffffu, m1, off));
            }
            if (l < 4) {   // lr==0 lanes hold cols 8nt+2l, +1
                const int c0 = 8 * nt + 2 * l;
                s[OFF_XIN + ndm * 64 + 32 + c0]     = fmaxf(m0 + s[OFF_B2 + c0], 0.f);
                s[OFF_XIN + ndm * 64 + 32 + c0 + 1] = fmaxf(m1 + s[OFF_B2 + c0 + 1], 0.f);
            }
        }
    }
    __syncthreads();   // S3: H dead everywhere, XIN complete

    // ---- stage W3 row-major swizzled into dead U ----
    for (int i4 = tid; i4 < 1024; i4 += 128) {
        const int h = i4 >> 4, cb = (i4 & 15) * 4;
        float4 v = __ldg((const float4*)(w21 + h * 64 + cb));
        *(float4*)&s[OFF_U + h * 72 + (cb ^ (((h >> 2) & 7) << 2))] = v;
    }
    __syncthreads();   // S4: W3 ready

    // ---- node MLP (fp32 SIMT): thread = (node tid/16, output tid%16) ----
    {
        const int nd = tid >> 4, q = tid & 15;
        const int c4 = q * 4;
        const int xq = (q & 7) << 2;
        float ha[4];
        #pragma unroll
        for (int j = 0; j < 4; j++) ha[j] = s[OFF_B3 + c4 + j];
        #pragma unroll
        for (int k4 = 0; k4 < 16; k4++) {
            const float4 xv = *(const float4*)&s[OFF_XIN + nd * 64 + 4 * k4];
            #pragma unroll
            for (int j = 0; j < 4; j++) {
                const float4 wv = *(const float4*)&s[OFF_U + (c4 + j) * 72 + ((4 * k4) ^ xq)];
                ha[j] = fmaf(xv.x, wv.x, fmaf(xv.y, wv.y, fmaf(xv.z, wv.z, fmaf(xv.w, wv.w, ha[j]))));
            }
        }
        // hid[8][64] aliases W2S (dead after GEMM2)
        *(float4*)&s[OFF_W2S + nd * 64 + c4] = make_float4(
            fmaxf(ha[0], 0.f), fmaxf(ha[1], 0.f), fmaxf(ha[2], 0.f), fmaxf(ha[3], 0.f));
        __syncwarp();

        float a3 = s[OFF_B4 + q];
        #pragma unroll
        for (int k4 = 0; k4 < 16; k4++) {
            const float4 hv = *(const float4*)&s[OFF_W2S + nd * 64 + 4 * k4];
            const float4 wv = __ldg((const float4*)(w22 + q * 64 + 4 * k4));
            a3 = fmaf(hv.x, wv.x, fmaf(hv.y, wv.y, fmaf(hv.z, wv.z, fmaf(hv.w, wv.w, a3))));
        }
        float v = fmaxf(a3, 0.f);
        float ssq = v * v;
        ssq += __shfl_xor_sync(0xffffffffu, ssq, 1);
        ssq += __shfl_xor_sync(0xffffffffu, ssq, 2);
        ssq += __shfl_xor_sync(0xffffffffu, ssq, 4);
        ssq += __shfl_xor_sync(0xffffffffu, ssq, 8);
        const float sn = sqrtf(ssq);
        if (sn > 1.f) v = v / sn;
        const size_t ng = (size_t)(n0 + nd);
        h_out[ng * 32 + q]      = v;
        h_out[ng * 32 + 16 + q] = s[OFF_XIN + nd * 64 + q];  // x[:, :16]
    }
}

extern "C" void kernel_launch(void* const* d_in, const int* in_sizes, int n_in,
                              void* d_out, int out_size)
{
    const float* x     = (const float*)d_in[0];
    const int*   eidx  = (const int*)d_in[1];     // [2, E] int32
    const float* eattr = (const float*)d_in[2];
    const float* w11 = (const float*)d_in[3];
    const float* b11 = (const float*)d_in[4];
    const float* w12 = (const float*)d_in[5];
    const float* b12 = (const float*)d_in[6];
    const float* w21 = (const float*)d_in[7];
    const float* b21 = (const float*)d_in[8];
    const float* w22 = (const float*)d_in[9];
    const float* b22 = (const float*)d_in[10];

    const int nN = in_sizes[0] / 32;          // 100000
    const int* srcp = eidx;                   // row 0 = src
    const int grid = nN / 8;                  // 12500 blocks (8 nodes each)
    const size_t smem = (size_t)SMEM_FLOATS * sizeof(float);

    cudaFuncSetAttribute(conv_kernel, cudaFuncAttributeMaxDynamicSharedMemorySize, (int)smem);

    float *b0, *b1;
    cudaGetSymbolAddress((void**)&b0, g_buf0);
    cudaGetSymbolAddress((void**)&b1, g_buf1);

    conv_kernel<<<grid, 128, smem>>>(x,  b0, srcp, eattr, w11, b11, w12, b12, w21, b21, w22, b22);
    conv_kernel<<<grid, 128, smem>>>(b0, b1, srcp, eattr, w11, b11, w12, b12, w21, b21, w22, b22);
    conv_kernel<<<grid, 128, smem>>>(b1, (float*)d_out, srcp, eattr, w11, b11, w12, b12, w21, b21, w22, b22);
}

// round 12
// speedup vs baseline: 1.7847x; 1.1430x over previous
#include <cuda_runtime.h>
#include <cstdint>

// ---------------------------------------------------------------------------
// Fused IGCNet conv, mma.sync 3xTF32 (mask-split) EVERYWHERE.
// Block: 8 nodes, 128 edges, 4 warps, occ 4 (51.5KB smem).
//   GEMM1: A[128,40] x W1[64,40]^T -> H[128,64] (swizzled smem)
//   GEMM2: H[128,64] x W2[32,64]^T -> C-frags -> shfl-xor segment max -> aggr
//   node MLP layer1: XIN[8(16),64] x W3[64,64]^T via mma (16 cols/warp)
//   node MLP layer2: hid[8(16),64] x W4[16,64]^T via mma (warps 0,1)
//   norm clip + concat x[:,:16] in a final 128-thread phase.
// R12: SIMT node MLP (dominant smem consumer: ~450 warp-cycles of LDS.128)
//      replaced by fragment-based mma (~110 scalar-LDS cycles).
// ---------------------------------------------------------------------------

#define NMAX 100000
__device__ float g_buf0[(size_t)NMAX * 32];
__device__ float g_buf1[(size_t)NMAX * 32];

// ---- smem layout (float offsets) ----
// U (9216): phase1 A[128][40](5120)+W1[64][40](@5120,2560); phase2 H[128][72];
//           phase3 W3[64][72](@0,4608)+W4[16][72](@4608,1152)
#define OFF_U     0
#define OFF_W2S   9216     // [32][72]=2304 W2; phase3: hid[16][68] (1088)
#define OFF_XIN   11520    // [16][64] rows 0-7 = [x_i(32) | aggr(32)], 8-15 pad
#define OFF_OUTS  12544    // [8][18] = 144
#define OFF_B1    12688
#define OFF_B2    12752
#define OFF_B3    12784
#define OFF_B4    12848
#define SMEM_FLOATS 12864  // 51456 B -> 4 blocks/SM

// mask split: hi = x with low 13 mantissa bits cleared, lo = x - hi (exact).
__device__ __forceinline__ void split_tf(float f, uint32_t& hi, uint32_t& lo) {
    hi = __float_as_uint(f) & 0xFFFFE000u;
    lo = __float_as_uint(f - __uint_as_float(hi));
}
__device__ __forceinline__ void mma8(float* c, const uint32_t* a, const uint32_t* b) {
    asm volatile(
        "mma.sync.aligned.m16n8k8.row.col.f32.tf32.tf32.f32 "
        "{%0,%1,%2,%3}, {%4,%5,%6,%7}, {%8,%9}, {%0,%1,%2,%3};"
        : "+f"(c[0]), "+f"(c[1]), "+f"(c[2]), "+f"(c[3])
        : "r"(a[0]), "r"(a[1]), "r"(a[2]), "r"(a[3]), "r"(b[0]), "r"(b[1]));
}
// swizzle for 40-col tiles (A, W1): cols 0..31 3-bit XOR, cols 32..39 1-bit
__device__ __forceinline__ int swA(int c, int x) {
    return (c < 32) ? (c ^ x) : (32 + ((c - 32) ^ (x & 4)));
}

__global__ void __launch_bounds__(128, 4) conv_kernel(
    const float* __restrict__ h_in, float* __restrict__ h_out,
    const int* __restrict__ src, const float* __restrict__ edge_attr,
    const float* __restrict__ w11, const float* __restrict__ b11,
    const float* __restrict__ w12, const float* __restrict__ b12,
    const float* __restrict__ w21, const float* __restrict__ b21,
    const float* __restrict__ w22, const float* __restrict__ b22)
{
    extern __shared__ float s[];
    const int tid = threadIdx.x;
    const int wid = tid >> 5, l = tid & 31;
    const int n0 = blockIdx.x * 8;

    // ---- stage W1/W2 (swizzled) + biases ----
    for (int i = tid; i < 2560; i += 128) {
        int n = i / 40, k = i - 40 * n;
        s[5120 + n * 40 + swA(k, ((n >> 2) & 7) << 2)] = w11[i];
    }
    for (int i = tid; i < 2048; i += 128) {
        int n = i >> 6, k = i & 63;
        s[OFF_W2S + n * 72 + (k ^ (((n >> 2) & 7) << 2))] = w12[i];
    }
    if (tid < 64) s[OFF_B1 + tid] = b11[tid];
    if (tid < 32) s[OFF_B2 + tid] = b12[tid];
    if (tid < 64) s[OFF_B3 + tid] = b21[tid];
    if (tid < 16) s[OFF_B4 + tid] = b22[tid];

    // ---- gather: A[e][k] stride 40 swizzled (thread = edge) ----
    {
        const long long eg = (long long)blockIdx.x * 128 + tid;
        const int si = src[eg];
        const float4* xr = (const float4*)(h_in + (size_t)si * 32);
        const int xa = ((tid >> 2) & 7) << 2;
        const int rb = OFF_U + tid * 40;
        #pragma unroll
        for (int j = 0; j < 8; j++)
            *(float4*)&s[rb + ((4 * j) ^ xa)] = xr[j];
        const float4* ar = (const float4*)(edge_attr + (size_t)eg * 8);
        #pragma unroll
        for (int j = 0; j < 2; j++)
            *(float4*)&s[rb + 32 + ((4 * j) ^ (xa & 4))] = ar[j];
        if (tid < 64) {  // destination-node features -> XIN[:, 0:32]
            int nd = tid >> 3, q = tid & 7;
            float4 v = *(const float4*)(h_in + (size_t)(n0 + nd) * 32 + q * 4);
            *(float4*)&s[OFF_XIN + nd * 64 + q * 4] = v;
        }
    }
    __syncthreads();   // S1

    const int e0 = 32 * wid;
    const int lr = l >> 2, lc = l & 3;
    int r0m[2], r1m[2], x0m[2], x1m[2];
    #pragma unroll
    for (int mt = 0; mt < 2; mt++) {
        r0m[mt] = e0 + 16 * mt + lr;
        r1m[mt] = r0m[mt] + 8;
        x0m[mt] = ((r0m[mt] >> 2) & 7) << 2;
        x1m[mt] = ((r1m[mt] >> 2) & 7) << 2;
    }

    // ---- GEMM1: A[128,40] x W1^T -> acc[2][8][4], 3xTF32 ----
    float acc[2][8][4];
    #pragma unroll
    for (int mt = 0; mt < 2; mt++)
        #pragma unroll
        for (int nt = 0; nt < 8; nt++)
            #pragma unroll
            for (int q = 0; q < 4; q++) acc[mt][nt][q] = 0.f;

    #pragma unroll
    for (int kc = 0; kc < 5; kc++) {
        const int c0 = 8 * kc + lc, c1 = c0 + 4;
        uint32_t ah[2][4], al[2][4];
        #pragma unroll
        for (int mt = 0; mt < 2; mt++) {
            split_tf(s[OFF_U + r0m[mt] * 40 + swA(c0, x0m[mt])], ah[mt][0], al[mt][0]);
            split_tf(s[OFF_U + r1m[mt] * 40 + swA(c0, x1m[mt])], ah[mt][1], al[mt][1]);
            split_tf(s[OFF_U + r0m[mt] * 40 + swA(c1, x0m[mt])], ah[mt][2], al[mt][2]);
            split_tf(s[OFF_U + r1m[mt] * 40 + swA(c1, x1m[mt])], ah[mt][3], al[mt][3]);
        }
        #pragma unroll
        for (int nt = 0; nt < 8; nt++) {
            const int wr = 8 * nt + lr;
            const int xw = ((wr >> 2) & 7) << 2;
            uint32_t bh[2], bl[2];
            split_tf(s[5120 + wr * 40 + swA(c0, xw)], bh[0], bl[0]);
            split_tf(s[5120 + wr * 40 + swA(c1, xw)], bh[1], bl[1]);
            #pragma unroll
            for (int mt = 0; mt < 2; mt++) {
                mma8(acc[mt][nt], ah[mt], bh);
                mma8(acc[mt][nt], al[mt], bh);
                mma8(acc[mt][nt], ah[mt], bl);
            }
        }
    }
    __syncthreads();   // S2: A/W1 reads done everywhere; U becomes H[128][72]

    // ---- H = relu(acc + b1) -> swizzled smem (float2 stores) ----
    #pragma unroll
    for (int mt = 0; mt < 2; mt++) {
        #pragma unroll
        for (int nt = 0; nt < 8; nt++) {
            const int c0 = 8 * nt + 2 * lc;
            const float bv0 = s[OFF_B1 + c0], bv1 = s[OFF_B1 + c0 + 1];
            float2 v01 = make_float2(fmaxf(acc[mt][nt][0] + bv0, 0.f),
                                     fmaxf(acc[mt][nt][1] + bv1, 0.f));
            float2 v23 = make_float2(fmaxf(acc[mt][nt][2] + bv0, 0.f),
                                     fmaxf(acc[mt][nt][3] + bv1, 0.f));
            *(float2*)&s[OFF_U + r0m[mt] * 72 + (c0 ^ x0m[mt])] = v01;
            *(float2*)&s[OFF_U + r1m[mt] * 72 + (c0 ^ x1m[mt])] = v23;
        }
    }
    __syncwarp();   // GEMM2 reads only this warp's own H rows

    // ---- GEMM2: H[128,64] x W2^T -> acc2[2][4][4], 3xTF32 ----
    float acc2[2][4][4];
    #pragma unroll
    for (int mt = 0; mt < 2; mt++)
        #pragma unroll
        for (int nt = 0; nt < 4; nt++)
            #pragma unroll
            for (int q = 0; q < 4; q++) acc2[mt][nt][q] = 0.f;

    #pragma unroll
    for (int kc = 0; kc < 8; kc++) {
        const int c0 = 8 * kc + lc, c1 = c0 + 4;
        uint32_t ah[2][4], al[2][4];
        #pragma unroll
        for (int mt = 0; mt < 2; mt++) {
            split_tf(s[OFF_U + r0m[mt] * 72 + (c0 ^ x0m[mt])], ah[mt][0], al[mt][0]);
            split_tf(s[OFF_U + r1m[mt] * 72 + (c0 ^ x1m[mt])], ah[mt][1], al[mt][1]);
            split_tf(s[OFF_U + r0m[mt] * 72 + (c1 ^ x0m[mt])], ah[mt][2], al[mt][2]);
            split_tf(s[OFF_U + r1m[mt] * 72 + (c1 ^ x1m[mt])], ah[mt][3], al[mt][3]);
        }
        #pragma unroll
        for (int nt = 0; nt < 4; nt++) {
            const int wr = 8 * nt + lr;
            const int xw = ((wr >> 2) & 7) << 2;
            uint32_t bh[2], bl[2];
            split_tf(s[OFF_W2S + wr * 72 + (c0 ^ xw)], bh[0], bl[0]);
            split_tf(s[OFF_W2S + wr * 72 + (c1 ^ xw)], bh[1], bl[1]);
            #pragma unroll
            for (int mt = 0; mt < 2; mt++) {
                mma8(acc2[mt][nt], ah[mt], bh);
                mma8(acc2[mt][nt], al[mt], bh);
                mma8(acc2[mt][nt], ah[mt], bl);
            }
        }
    }

    // ---- segment max via shfl_xor (tile mt == node 2*wid+mt) ----
    #pragma unroll
    for (int mt = 0; mt < 2; mt++) {
        const int ndm = 2 * wid + mt;
        #pragma unroll
        for (int nt = 0; nt < 4; nt++) {
            float m0 = fmaxf(acc2[mt][nt][0], acc2[mt][nt][2]);
            float m1 = fmaxf(acc2[mt][nt][1], acc2[mt][nt][3]);
            #pragma unroll
            for (int off = 4; off <= 16; off <<= 1) {
                m0 = fmaxf(m0, __shfl_xor_sync(0xffffffffu, m0, off));
                m1 = fmaxf(m1, __shfl_xor_sync(0xffffffffu, m1, off));
            }
            if (l < 4) {   // lr==0 lanes hold cols 8nt+2l, +1
                const int c0 = 8 * nt + 2 * l;
                s[OFF_XIN + ndm * 64 + 32 + c0]     = fmaxf(m0 + s[OFF_B2 + c0], 0.f);
                s[OFF_XIN + ndm * 64 + 32 + c0 + 1] = fmaxf(m1 + s[OFF_B2 + c0 + 1], 0.f);
            }
        }
    }
    __syncthreads();   // S3: H dead everywhere, XIN complete

    // ---- stage W3[64][64] + W4[16][64] row-major swizzled into dead U ----
    for (int i4 = tid; i4 < 1024; i4 += 128) {
        const int h = i4 >> 4, cb = (i4 & 15) * 4;
        float4 v = __ldg((const float4*)(w21 + h * 64 + cb));
        *(float4*)&s[OFF_U + h * 72 + (cb ^ (((h >> 2) & 7) << 2))] = v;
    }
    for (int i4 = tid; i4 < 256; i4 += 128) {
        const int n = i4 >> 4, cb = (i4 & 15) * 4;
        float4 v = __ldg((const float4*)(w22 + n * 64 + cb));
        *(float4*)&s[OFF_U + 4608 + n * 72 + (cb ^ (((n >> 2) & 7) << 2))] = v;
    }
    __syncthreads();   // S4: W3/W4 ready

    // ---- node MLP layer1 via mma: warp w -> output cols 16w..16w+15 ----
    // A = XIN[16,64] (rows 8-15 garbage, row-separable); B = W3 rows.
    {
        float acc3[2][4];
        #pragma unroll
        for (int t = 0; t < 2; t++)
            #pragma unroll
            for (int q = 0; q < 4; q++) acc3[t][q] = 0.f;
        #pragma unroll
        for (int kc = 0; kc < 8; kc++) {
            const int c0 = 8 * kc + lc, c1 = c0 + 4;
            uint32_t ah[4], al[4];
            split_tf(s[OFF_XIN + lr * 64 + c0],       ah[0], al[0]);
            split_tf(s[OFF_XIN + (lr + 8) * 64 + c0], ah[1], al[1]);
            split_tf(s[OFF_XIN + lr * 64 + c1],       ah[2], al[2]);
            split_tf(s[OFF_XIN + (lr + 8) * 64 + c1], ah[3], al[3]);
            #pragma unroll
            for (int t = 0; t < 2; t++) {
                const int wr = 8 * (2 * wid + t) + lr;
                const int xw = ((wr >> 2) & 7) << 2;
                uint32_t bh[2], bl[2];
                split_tf(s[OFF_U + wr * 72 + (c0 ^ xw)], bh[0], bl[0]);
                split_tf(s[OFF_U + wr * 72 + (c1 ^ xw)], bh[1], bl[1]);
                mma8(acc3[t], ah, bh);
                mma8(acc3[t], al, bh);
                mma8(acc3[t], ah, bl);
            }
        }
        // hid = relu(acc3 + b3) -> hid[16][68] at OFF_W2S (rows 0-7 valid)
        #pragma unroll
        for (int t = 0; t < 2; t++) {
            const int c0 = 8 * (2 * wid + t) + 2 * lc;
            float2 v = make_float2(fmaxf(acc3[t][0] + s[OFF_B3 + c0], 0.f),
                                   fmaxf(acc3[t][1] + s[OFF_B3 + c0 + 1], 0.f));
            *(float2*)&s[OFF_W2S + lr * 68 + c0] = v;
        }
    }
    __syncthreads();   // S5: hid ready

    // ---- node MLP layer2 via mma: warps 0,1 -> output cols 8w..8w+7 ----
    if (wid < 2) {
        float acc4[4] = {0.f, 0.f, 0.f, 0.f};
        #pragma unroll
        for (int kc = 0; kc < 8; kc++) {
            const int c0 = 8 * kc + lc, c1 = c0 + 4;
            uint32_t ah[4], al[4];
            split_tf(s[OFF_W2S + lr * 68 + c0],       ah[0], al[0]);
            split_tf(s[OFF_W2S + (lr + 8) * 68 + c0], ah[1], al[1]);
            split_tf(s[OFF_W2S + lr * 68 + c1],       ah[2], al[2]);
            split_tf(s[OFF_W2S + (lr + 8) * 68 + c1], ah[3], al[3]);
            const int wr = 8 * wid + lr;
            const int xw = ((wr >> 2) & 7) << 2;
            uint32_t bh[2], bl[2];
            split_tf(s[OFF_U + 4608 + wr * 72 + (c0 ^ xw)], bh[0], bl[0]);
            split_tf(s[OFF_U + 4608 + wr * 72 + (c1 ^ xw)], bh[1], bl[1]);
            mma8(acc4, ah, bh);
            mma8(acc4, al, bh);
            mma8(acc4, ah, bl);
        }
        const int c0 = 8 * wid + 2 * lc;
        float2 v = make_float2(fmaxf(acc4[0] + s[OFF_B4 + c0], 0.f),
                               fmaxf(acc4[1] + s[OFF_B4 + c0 + 1], 0.f));
        *(float2*)&s[OFF_OUTS + lr * 18 + c0] = v;
    }
    __syncthreads();   // S6: out_s ready

    // ---- norm clip + output (thread = (node tid/16, col tid%16)) ----
    {
        const int nd = tid >> 4, q = tid & 15;
        float v = s[OFF_OUTS + nd * 18 + q];
        float ssq = v * v;
        ssq += __shfl_xor_sync(0xffffffffu, ssq, 1);
        ssq += __shfl_xor_sync(0xffffffffu, ssq, 2);
        ssq += __shfl_xor_sync(0xffffffffu, ssq, 4);
        ssq += __shfl_xor_sync(0xffffffffu, ssq, 8);
        const float sn = sqrtf(ssq);
        if (sn > 1.f) v = v / sn;
        const size_t ng = (size_t)(n0 + nd);
        h_out[ng * 32 + q]      = v;
        h_out[ng * 32 + 16 + q] = s[OFF_XIN + nd * 64 + q];  // x[:, :16]
    }
}

extern "C" void kernel_launch(void* const* d_in, const int* in_sizes, int n_in,
                              void* d_out, int out_size)
{
    const float* x     = (const float*)d_in[0];
    const int*   eidx  = (const int*)d_in[1];     // [2, E] int32
    const float* eattr = (const float*)d_in[2];
    const float* w11 = (const float*)d_in[3];
    const float* b11 = (const float*)d_in[4];
    const float* w12 = (const float*)d_in[5];
    const float* b12 = (const float*)d_in[6];
    const float* w21 = (const float*)d_in[7];
    const float* b21 = (const float*)d_in[8];
    const float* w22 = (const float*)d_in[9];
    const float* b22 = (const float*)d_in[10];

    const int nN = in_sizes[0] / 32;          // 100000
    const int* srcp = eidx;                   // row 0 = src
    const int grid = nN / 8;                  // 12500 blocks (8 nodes each)
    const size_t smem = (size_t)SMEM_FLOATS * sizeof(float);

    cudaFuncSetAttribute(conv_kernel, cudaFuncAttributeMaxDynamicSharedMemorySize, (int)smem);

    float *b0, *b1;
    cudaGetSymbolAddress((void**)&b0, g_buf0);
    cudaGetSymbolAddress((void**)&b1, g_buf1);

    conv_kernel<<<grid, 128, smem>>>(x,  b0, srcp, eattr, w11, b11, w12, b12, w21, b21, w22, b22);
    conv_kernel<<<grid, 128, smem>>>(b0, b1, srcp, eattr, w11, b11, w12, b12, w21, b21, w22, b22);
    conv_kernel<<<grid, 128, smem>>>(b1, (float*)d_out, srcp, eattr, w11, b11, w12, b12, w21, b21, w22, b22);
}